// round 3
// baseline (speedup 1.0000x reference)
#include <cuda_runtime.h>
#include <math.h>

#define BATCH 2
#define TLEN  2048
#define DIM   256
#define CD    64
#define TC    512
#define SEQ   (TC + TLEN)
#define KTOP  8

static __device__ __forceinline__ float fneginf() { return __int_as_float(0xff800000); }

// ----------------------------- scratch ------------------------------------
__device__ float g_Q  [BATCH * TLEN * DIM];    // roped Q, [b][t][h*64+c]
__device__ float g_K  [BATCH * SEQ * CD];      // roped K over concat axis
__device__ float g_V  [BATCH * SEQ * CD];
__device__ float g_QI [BATCH * TLEN * 128];
__device__ float g_WIw[BATCH * TLEN * 4];
__device__ float g_KI [BATCH * TC * 32];
__device__ float g_I  [BATCH * TLEN * TC];
__device__ int   g_top[BATCH * TLEN * KTOP];
__device__ float g_cos[SEQ * 32];
__device__ float g_sin[SEQ * 32];

// ----------------------------- K0: rope tables -----------------------------
__global__ void k_tables()
{
    int idx = blockIdx.x * blockDim.x + threadIdx.x;
    if (idx >= SEQ * 32) return;
    int pos = idx >> 5, j = idx & 31;
    float invf = (float)pow(10000.0, -(double)j / 32.0);   // f32-rounded inv_freq
    float ang  = (float)pos * invf;                        // f32 angle (matches ref)
    double a = (double)ang;
    g_cos[idx] = (float)cos(a);
    g_sin[idx] = (float)sin(a);
}

// ------------------ K1: per-token GEMMs + RMS + RoPE -----------------------
// 16 tokens/block, 384 threads: cols 0..255 -> W_Q, 256..319 -> W_KV,
// 320..383 -> W_DQ. Epilogue: Q rms/rope, sliding K/V rms/rope, Q_I, W_Iw.
__global__ __launch_bounds__(384) void k_token(
    const float* __restrict__ H,
    const float* __restrict__ W_DQ, const float* __restrict__ W_IUQ,
    const float* __restrict__ W_w,  const float* __restrict__ W_Q,
    const float* __restrict__ W_KV,
    const float* __restrict__ gq, const float* __restrict__ gk,
    const float* __restrict__ gv)
{
    __shared__ float h_s[DIM * 16];      // [k][tok]
    __shared__ float o_s[16 * 384];      // [tok][col]
    __shared__ float rq_s[64];
    __shared__ float rkv_s[16];
    const int tid = threadIdx.x;
    const int b  = blockIdx.x >> 7;            // / 128
    const int t0 = (blockIdx.x & 127) << 4;
    const float* Hb = H + ((size_t)b * TLEN + t0) * DIM;

    for (int i = tid; i < 16 * DIM; i += 384)
        h_s[(i & 255) * 16 + (i >> 8)] = Hb[i];
    __syncthreads();

    float acc[16];
#pragma unroll
    for (int i = 0; i < 16; i++) acc[i] = 0.f;
    const float* Wcol; int ldw;
    if (tid < 256)      { Wcol = W_Q  + tid;         ldw = 256; }
    else if (tid < 320) { Wcol = W_KV + (tid - 256); ldw = 64;  }
    else                { Wcol = W_DQ + (tid - 320); ldw = 64;  }
#pragma unroll 4
    for (int k = 0; k < DIM; k++) {
        float w = Wcol[(size_t)k * ldw];
        const float4* hr = (const float4*)(h_s + k * 16);
#pragma unroll
        for (int q = 0; q < 4; q++) {
            float4 a = hr[q];
            acc[4*q+0] += a.x * w; acc[4*q+1] += a.y * w;
            acc[4*q+2] += a.z * w; acc[4*q+3] += a.w * w;
        }
    }
#pragma unroll
    for (int tok = 0; tok < 16; tok++) o_s[tok * 384 + tid] = acc[tok];
    __syncthreads();

    if (tid < 64) {                       // Q rms per (tok, head)
        int tok = tid >> 2, h = tid & 3;
        float ss = 0.f;
        for (int c = 0; c < CD; c++) { float v = o_s[tok*384 + h*64 + c]; ss += v*v; }
        rq_s[tid] = rsqrtf(ss * (1.f/64.f) + 1e-6f);
    } else if (tid < 80) {                // KV rms per tok
        int tok = tid - 64;
        float ss = 0.f;
        for (int c = 0; c < CD; c++) { float v = o_s[tok*384 + 256 + c]; ss += v*v; }
        rkv_s[tok] = rsqrtf(ss * (1.f/64.f) + 1e-6f);
    }
    __syncthreads();

    // Q: scale by rms*g_q then rope at pos t
    for (int i = tid; i < 16 * 256; i += 384) {
        int tok = i >> 8, cc = i & 255;
        int h = cc >> 6, c = cc & 63, j = c & 31;
        int t = t0 + tok;
        float r = rq_s[tok * 4 + h];
        float x1 = o_s[tok*384 + h*64 + j]      * r * gq[h*64 + j];
        float x2 = o_s[tok*384 + h*64 + j + 32] * r * gq[h*64 + j + 32];
        float cs = g_cos[t*32 + j], sn = g_sin[t*32 + j];
        g_Q[((size_t)b*TLEN + t) * 256 + cc] = (c < 32) ? (x1*cs - x2*sn)
                                                        : (x1*sn + x2*cs);
    }
    // sliding K/V at pos TC + t
    for (int i = tid; i < 16 * 64; i += 384) {
        int tok = i >> 6, c = i & 63, j = c & 31;
        int t = t0 + tok, pos = TC + t;
        float r = rkv_s[tok];
        float x1 = o_s[tok*384 + 256 + j]      * r;
        float x2 = o_s[tok*384 + 256 + j + 32] * r;
        float cs = g_cos[pos*32 + j], sn = g_sin[pos*32 + j];
        float k1 = x1*gk[j], k2 = x2*gk[j+32];
        float v1 = x1*gv[j], v2 = x2*gv[j+32];
        size_t o = ((size_t)b*SEQ + pos) * 64 + c;
        g_K[o] = (c < 32) ? (k1*cs - k2*sn) : (k1*sn + k2*cs);
        g_V[o] = (c < 32) ? (v1*cs - v2*sn) : (v1*sn + v2*cs);
    }
    // Q_I = H_dc @ W_IUQ  (H_dc = cols 320..383)
    for (int i = tid; i < 16 * 128; i += 384) {
        int tok = i >> 7, c = i & 127;
        const float* hd = &o_s[tok*384 + 320];
        float a = 0.f;
#pragma unroll 4
        for (int k = 0; k < 64; k++) a += hd[k] * W_IUQ[k*128 + c];
        g_QI[((size_t)b*TLEN + t0 + tok) * 128 + c] = a;
    }
    if (tid < 64) {                        // W_Iw = H_dc @ W_w
        int tok = tid >> 2, c = tid & 3;
        const float* hd = &o_s[tok*384 + 320];
        float a = 0.f;
        for (int k = 0; k < 64; k++) a += hd[k] * W_w[k*4 + c];
        g_WIw[((size_t)b*TLEN + t0 + tok) * 4 + c] = a;
    }
}

// ------------------ K2: window compression ---------------------------------
// 8 windows/block (rows 4*s0 .. 4*s0+35 shared), 256 threads; threads 0..191
// compute 96 cols x 4 windows each (two ds-groups of 96 threads).
__global__ __launch_bounds__(256) void k_compress(
    const float* __restrict__ H,
    const float* __restrict__ Wc_comp, const float* __restrict__ Wc_idx,
    const float* __restrict__ gk, const float* __restrict__ gv)
{
    __shared__ float win[36 * DIM];
    __shared__ float comp_s[8 * 64];
    __shared__ float rms_s[8];
    const int tid = threadIdx.x;
    const int b  = blockIdx.x >> 6;           // / 64
    const int s0 = (blockIdx.x & 63) << 3;
    const int row0 = 4 * s0;

    for (int i = tid; i < 36 * DIM; i += 256) {
        int r = row0 + (i >> 8);
        win[i] = (r < TLEN) ? H[((size_t)b*TLEN + r) * DIM + (i & 255)] : 0.f;
    }
    __syncthreads();

    if (tid < 192) {
        int grp = tid / 96;              // ds range grp*4 .. grp*4+3
        int col = tid % 96;
        const float* Wcol; int ldw;
        if (col < 64) { Wcol = Wc_comp + col;       ldw = 64; }
        else          { Wcol = Wc_idx + (col - 64); ldw = 32; }
        float a0 = 0.f, a1 = 0.f, a2 = 0.f, a3 = 0.f;
        int ds0 = grp * 4;
        for (int k4 = 0; k4 < 512; k4++) {
            float w0 = Wcol[(size_t)(4*k4+0) * ldw];
            float w1 = Wcol[(size_t)(4*k4+1) * ldw];
            float w2 = Wcol[(size_t)(4*k4+2) * ldw];
            float w3 = Wcol[(size_t)(4*k4+3) * ldw];
            int lrow = k4 >> 6;          // row within window
            int coff = (k4 & 63) << 2;   // col within row
#pragma unroll
            for (int d = 0; d < 4; d++) {
                const float4 wv = *(const float4*)&win[(4*(ds0+d) + lrow) * DIM + coff];
                float s = wv.x*w0 + wv.y*w1 + wv.z*w2 + wv.w*w3;
                if (d == 0) a0 += s; else if (d == 1) a1 += s;
                else if (d == 2) a2 += s; else a3 += s;
            }
        }
        float av[4] = {a0, a1, a2, a3};
        if (col < 64) {
#pragma unroll
            for (int d = 0; d < 4; d++) comp_s[(ds0 + d) * 64 + col] = av[d];
        } else {
#pragma unroll
            for (int d = 0; d < 4; d++)
                g_KI[((size_t)b*TC + s0 + ds0 + d) * 32 + (col - 64)] = av[d];
        }
    }
    __syncthreads();
    if (tid < 8) {
        float ss = 0.f;
        for (int c = 0; c < 64; c++) { float v = comp_s[tid*64 + c]; ss += v*v; }
        rms_s[tid] = rsqrtf(ss * (1.f/64.f) + 1e-6f);
    }
    __syncthreads();
    for (int i = tid; i < 8 * 64; i += 256) {
        int ds = i >> 6, c = i & 63, j = c & 31;
        int pos = s0 + ds;
        float r = rms_s[ds];
        float x1 = comp_s[ds*64 + j] * r, x2 = comp_s[ds*64 + j + 32] * r;
        float cs = g_cos[pos*32 + j], sn = g_sin[pos*32 + j];
        float k1 = x1*gk[j], k2 = x2*gk[j+32];
        float v1 = x1*gv[j], v2 = x2*gv[j+32];
        size_t o = ((size_t)b*SEQ + pos) * 64 + c;
        g_K[o] = (c < 32) ? (k1*cs - k2*sn) : (k1*sn + k2*cs);
        g_V[o] = (c < 32) ? (v1*cs - v2*sn) : (v1*sn + v2*cs);
    }
}

// ------------------ K3: index scores I_ts (16 tok x 128 s tile) ------------
__global__ __launch_bounds__(256) void k_score()
{
    __shared__ float qi_s[16 * 132];     // pad 132 (16B-aligned rows)
    __shared__ float ki_s[128 * 32];
    __shared__ float i_s[16 * 128];
    const int tid = threadIdx.x;
    const int blk = blockIdx.x;
    const int b  = blk >> 9;                       // / 512
    const int r  = blk & 511;
    const int t0 = (r >> 2) << 4;                  // 128 token-tiles
    const int s0 = (r & 3) << 7;                   // 4 s-tiles

    for (int i = tid; i < 16 * 128; i += 256)
        qi_s[(i >> 7) * 132 + (i & 127)] = g_QI[((size_t)b*TLEN + t0 + (i >> 7)) * 128 + (i & 127)];
    for (int i = tid; i < 128 * 32; i += 256)
        ki_s[i] = g_KI[((size_t)b*TC + s0) * 32 + i];
    __syncthreads();

    const int tok = tid & 15;
    const int sg  = tid >> 4;
    float acc[4][8];
#pragma unroll
    for (int h = 0; h < 4; h++)
#pragma unroll
        for (int j = 0; j < 8; j++) acc[h][j] = 0.f;

#pragma unroll
    for (int c4 = 0; c4 < 8; c4++) {
        float4 q4[4];
#pragma unroll
        for (int h = 0; h < 4; h++)
            q4[h] = *(const float4*)&qi_s[tok*132 + h*32 + c4*4];
#pragma unroll
        for (int j = 0; j < 8; j++) {
            const float4 kv = *(const float4*)&ki_s[(sg*8 + j)*32 + c4*4];
#pragma unroll
            for (int h = 0; h < 4; h++)
                acc[h][j] += q4[h].x*kv.x + q4[h].y*kv.y + q4[h].z*kv.z + q4[h].w*kv.w;
        }
    }
    float w0 = g_WIw[((size_t)b*TLEN + t0 + tok)*4 + 0];
    float w1 = g_WIw[((size_t)b*TLEN + t0 + tok)*4 + 1];
    float w2 = g_WIw[((size_t)b*TLEN + t0 + tok)*4 + 2];
    float w3 = g_WIw[((size_t)b*TLEN + t0 + tok)*4 + 3];
#pragma unroll
    for (int j = 0; j < 8; j++) {
        float v = w0*fmaxf(acc[0][j],0.f) + w1*fmaxf(acc[1][j],0.f)
                + w2*fmaxf(acc[2][j],0.f) + w3*fmaxf(acc[3][j],0.f);
        i_s[tok*128 + sg*8 + j] = v;
    }
    __syncthreads();
    // coalesced writeout: 8 contiguous floats per thread
    {
        int base = tid * 8;
        int tt = base >> 7, ss = base & 127;
        float4 v0 = *(const float4*)&i_s[base];
        float4 v1 = *(const float4*)&i_s[base + 4];
        float* dst = &g_I[((size_t)b*TLEN + t0 + tt) * TC + s0 + ss];
        *(float4*)dst = v0;
        *(float4*)(dst + 4) = v1;
    }
}

// ------------------ K4: top-k (exact jax.lax.top_k semantics) --------------
static __device__ __forceinline__ unsigned long long packkey(float v, int s)
{
    unsigned u = __float_as_uint(v);
    u = (u & 0x80000000u) ? ~u : (u | 0x80000000u);
    return ((unsigned long long)u << 32) | (unsigned)(511 - s);
}

__global__ __launch_bounds__(256) void k_topk()
{
    const int tid = threadIdx.x;
    const int w = tid >> 5, l = tid & 31;
    const int b  = blockIdx.x >> 8;            // / 256
    const int t  = ((blockIdx.x & 255) << 3) + w;
    const float* Irow = &g_I[((size_t)b*TLEN + t) * TC];

    unsigned long long keys[16];
#pragma unroll
    for (int k = 0; k < 16; k++) {
        int s = l + 32*k;
        float v = (4*s <= t) ? Irow[s] : fneginf();
        keys[k] = packkey(v, s);
    }
#pragma unroll 1
    for (int i = 0; i < KTOP; i++) {
        unsigned long long best = 0ull;
#pragma unroll
        for (int k = 0; k < 16; k++) best = max(best, keys[k]);
#pragma unroll
        for (int off = 16; off; off >>= 1)
            best = max(best, __shfl_xor_sync(0xffffffffu, best, off));
        int s_win = 511 - (int)(best & 0xffffffffull);
        if (l == 0) g_top[((size_t)b*TLEN + t) * KTOP + i] = s_win;
        if ((s_win & 31) == l) keys[s_win >> 5] = 0ull;
    }
}

// ------------------ K5: sparse attention + inverse rope + projections ------
// 512 threads, 16 tokens/block, one warp per token for attention.
__global__ __launch_bounds__(512) void k_attn(
    const float* __restrict__ Wg0, const float* __restrict__ bg0,
    const float* __restrict__ Wg1, const float* __restrict__ bg1,
    const float* __restrict__ Wout, const float* __restrict__ bout,
    float* __restrict__ OUT)
{
    __shared__ float qo_s[16 * 256];       // Q tile, then (aliased) rotated O tile
    __shared__ float g_s[16 * 128];
    __shared__ float p_s[16 * 4 * 24];
    __shared__ int   pos_s[16 * 24];
    const int tid = threadIdx.x;
    const int b  = blockIdx.x >> 7;
    const int t0 = (blockIdx.x & 127) << 4;

    for (int i = tid; i < 16 * 256; i += 512)
        qo_s[i] = g_Q[((size_t)b*TLEN + t0) * 256 + i];
    __syncthreads();

    {   // ---- attention: warp w -> token t0+w ----
        const int w = tid >> 5, l = tid & 31;
        const int t = t0 + w;
        const int nsl = (t + 1 < 16) ? (t + 1) : 16;
        const int nkey = 8 + nsl;
        int row = -1;
        if (l < 8)          row = g_top[((size_t)b*TLEN + t) * KTOP + l];
        else if (l < nkey)  row = TC + t - (l - 8);
        if (l < 24) pos_s[w*24 + l] = row;

        float dh[4] = {0.f, 0.f, 0.f, 0.f};
        if (row >= 0) {
            const float4* kp = (const float4*)(g_K + ((size_t)b*SEQ + row) * 64);
#pragma unroll
            for (int c4 = 0; c4 < 16; c4++) {
                float4 kv = kp[c4];
#pragma unroll
                for (int h = 0; h < 4; h++) {
                    float4 q4 = *(const float4*)&qo_s[w*256 + h*64 + c4*4];
                    dh[h] += q4.x*kv.x + q4.y*kv.y + q4.z*kv.z + q4.w*kv.w;
                }
            }
        }
#pragma unroll
        for (int h = 0; h < 4; h++) {
            float s = (row >= 0) ? dh[h] * 0.125f : fneginf();
            float m = s;
#pragma unroll
            for (int off = 16; off; off >>= 1)
                m = fmaxf(m, __shfl_xor_sync(0xffffffffu, m, off));
            float e = expf(s - m);
            float sum = e;
#pragma unroll
            for (int off = 16; off; off >>= 1)
                sum += __shfl_xor_sync(0xffffffffu, sum, off);
            float p = e / sum;
            if (l < 24) p_s[w*96 + h*24 + l] = p;
        }
        __syncwarp();

        // O accumulation: lane l owns dims (l, l+32) for all 4 heads
        float o1[4] = {0,0,0,0}, o2[4] = {0,0,0,0};
        for (int j = 0; j < nkey; j++) {
            int rj = pos_s[w*24 + j];
            const float* vp = g_V + ((size_t)b*SEQ + rj) * 64;
            float v1 = vp[l], v2 = vp[l + 32];
#pragma unroll
            for (int h = 0; h < 4; h++) {
                float p = p_s[w*96 + h*24 + j];
                o1[h] += p * v1;
                o2[h] += p * v2;
            }
        }
        float cs = g_cos[t*32 + l], sn = g_sin[t*32 + l];
        __syncwarp();   // all lanes done reading qo_s[w] before overwrite
#pragma unroll
        for (int h = 0; h < 4; h++) {
            qo_s[w*256 + h*64 + l]      =  o1[h]*cs + o2[h]*sn;
            qo_s[w*256 + h*64 + 32 + l] = -o1[h]*sn + o2[h]*cs;
        }
    }
    __syncthreads();

    // ---- gate projections: g = [O0@Wg0+bg0 ; O1@Wg1+bg1] ----
    {
        const int col = tid & 127;
        const int tq  = tid >> 7;               // 4 tokens each
        const int c   = col & 63;
        const float* Wg = (col < 64) ? Wg0 : Wg1;
        const float  bb = (col < 64) ? bg0[c] : bg1[c];
        const int obase = (col < 64) ? 0 : 128;
        float a[4] = {bb, bb, bb, bb};
#pragma unroll 4
        for (int k = 0; k < 128; k++) {
            float wv = Wg[k*64 + c];
#pragma unroll
            for (int u = 0; u < 4; u++)
                a[u] += qo_s[(tq*4 + u)*256 + obase + k] * wv;
        }
#pragma unroll
        for (int u = 0; u < 4; u++) g_s[(tq*4 + u)*128 + col] = a[u];
    }
    __syncthreads();

    // ---- final: out = p_all @ Wout + bout ----
    {
        const int col = tid & 255;
        const int tq  = tid >> 8;               // 8 tokens each
        float bb = bout[col];
        float a[8] = {bb, bb, bb, bb, bb, bb, bb, bb};
#pragma unroll 4
        for (int k = 0; k < 128; k++) {
            float wv = Wout[k*256 + col];
#pragma unroll
            for (int u = 0; u < 8; u++)
                a[u] += g_s[(tq*8 + u)*128 + k] * wv;
        }
#pragma unroll
        for (int u = 0; u < 8; u++)
            OUT[((size_t)b*TLEN + t0 + tq*8 + u) * DIM + col] = a[u];
    }
}

// ----------------------------- launcher ------------------------------------
extern "C" void kernel_launch(void* const* d_in, const int* in_sizes, int n_in,
                              void* d_out, int out_size)
{
    const float* H       = (const float*)d_in[0];
    const float* Wc_comp = (const float*)d_in[1];
    const float* Wc_idx  = (const float*)d_in[2];
    const float* W_DQ    = (const float*)d_in[3];
    const float* W_IUQ   = (const float*)d_in[4];
    const float* W_w     = (const float*)d_in[5];
    const float* W_Q     = (const float*)d_in[6];
    const float* W_KV    = (const float*)d_in[7];
    const float* gq      = (const float*)d_in[8];
    const float* gk      = (const float*)d_in[9];
    const float* gv      = (const float*)d_in[10];
    const float* Wg0     = (const float*)d_in[11];
    const float* bg0     = (const float*)d_in[12];
    const float* Wg1     = (const float*)d_in[13];
    const float* bg1     = (const float*)d_in[14];
    const float* Wout    = (const float*)d_in[15];
    const float* bout    = (const float*)d_in[16];
    float* OUT = (float*)d_out;

    k_tables<<<(SEQ * 32 + 255) / 256, 256>>>();
    k_token<<<BATCH * (TLEN / 16), 384>>>(H, W_DQ, W_IUQ, W_w, W_Q, W_KV, gq, gk, gv);
    k_compress<<<BATCH * (TC / 8), 256>>>(H, Wc_comp, Wc_idx, gk, gv);
    k_score<<<BATCH * (TLEN / 16) * (TC / 128), 256>>>();
    k_topk<<<BATCH * (TLEN / 8), 256>>>();
    k_attn<<<BATCH * (TLEN / 16), 512>>>(Wg0, bg0, Wg1, bg1, Wout, bout, OUT);
}

// round 4
// speedup vs baseline: 2.0760x; 2.0760x over previous
#include <cuda_runtime.h>
#include <math.h>

#define BATCH 2
#define TLEN  2048
#define DIM   256
#define CD    64
#define TC    512
#define SEQ   (TC + TLEN)
#define KTOP  8

static __device__ __forceinline__ float fneginf() { return __int_as_float(0xff800000); }

// ----------------------------- scratch ------------------------------------
__device__ float g_Q  [BATCH * TLEN * DIM];    // roped Q, [b][t][h*64+c]
__device__ float g_K  [BATCH * SEQ * CD];      // roped K over concat axis
__device__ float g_V  [BATCH * SEQ * CD];
__device__ float g_QI [BATCH * TLEN * 128];
__device__ float g_WIw[BATCH * TLEN * 4];
__device__ float g_KI [BATCH * TC * 32];
__device__ int   g_top[BATCH * TLEN * KTOP];
__device__ float g_cos[SEQ * 32];
__device__ float g_sin[SEQ * 32];

// ----------------------------- K0: rope tables -----------------------------
__global__ void k_tables()
{
    int idx = blockIdx.x * blockDim.x + threadIdx.x;
    if (idx >= SEQ * 32) return;
    int pos = idx >> 5, j = idx & 31;
    float invf = (float)pow(10000.0, -(double)j / 32.0);   // f32-rounded inv_freq
    float ang  = (float)pos * invf;                        // f32 angle (matches ref)
    double a = (double)ang;
    g_cos[idx] = (float)cos(a);
    g_sin[idx] = (float)sin(a);
}

// ------------------ K1: fused token GEMMs + window compression -------------
// blocks [0,256): token path  — 16 tokens/block, 384 threads
// blocks [256,384): compress  — 8 windows/block, 384 threads (2 grp x 2 ksplit)
__global__ __launch_bounds__(384) void k_pre(
    const float* __restrict__ H,
    const float* __restrict__ Wc_comp, const float* __restrict__ Wc_idx,
    const float* __restrict__ W_DQ, const float* __restrict__ W_IUQ,
    const float* __restrict__ W_w,  const float* __restrict__ W_Q,
    const float* __restrict__ W_KV,
    const float* __restrict__ gq, const float* __restrict__ gk,
    const float* __restrict__ gv)
{
    __shared__ float sm[11272];
    const int tid = threadIdx.x;

    if (blockIdx.x < 256) {
        // ======================= token path ================================
        float* h_s   = sm;          // [k][tok]  4096
        float* o_s   = sm + 4096;   // [tok][col] 6144
        float* rq_s  = sm + 10240;  // 64
        float* rkv_s = sm + 10304;  // 16
        const int b  = blockIdx.x >> 7;
        const int t0 = (blockIdx.x & 127) << 4;
        const float* Hb = H + ((size_t)b * TLEN + t0) * DIM;

        for (int i = tid; i < 16 * DIM; i += 384)
            h_s[(i & 255) * 16 + (i >> 8)] = Hb[i];
        __syncthreads();

        float acc[16];
#pragma unroll
        for (int i = 0; i < 16; i++) acc[i] = 0.f;
        const float* Wcol; int ldw;
        if (tid < 256)      { Wcol = W_Q  + tid;         ldw = 256; }
        else if (tid < 320) { Wcol = W_KV + (tid - 256); ldw = 64;  }
        else                { Wcol = W_DQ + (tid - 320); ldw = 64;  }
#pragma unroll 4
        for (int k = 0; k < DIM; k++) {
            float w = Wcol[(size_t)k * ldw];
            const float4* hr = (const float4*)(h_s + k * 16);
#pragma unroll
            for (int q = 0; q < 4; q++) {
                float4 a = hr[q];
                acc[4*q+0] += a.x * w; acc[4*q+1] += a.y * w;
                acc[4*q+2] += a.z * w; acc[4*q+3] += a.w * w;
            }
        }
#pragma unroll
        for (int tok = 0; tok < 16; tok++) o_s[tok * 384 + tid] = acc[tok];
        __syncthreads();

        if (tid < 64) {                       // Q rms per (tok, head)
            int tok = tid >> 2, h = tid & 3;
            float ss = 0.f;
            for (int c = 0; c < CD; c++) { float v = o_s[tok*384 + h*64 + c]; ss += v*v; }
            rq_s[tid] = rsqrtf(ss * (1.f/64.f) + 1e-6f);
        } else if (tid < 80) {                // KV rms per tok
            int tok = tid - 64;
            float ss = 0.f;
            for (int c = 0; c < CD; c++) { float v = o_s[tok*384 + 256 + c]; ss += v*v; }
            rkv_s[tok] = rsqrtf(ss * (1.f/64.f) + 1e-6f);
        }
        __syncthreads();

        // Q: scale by rms*g_q then rope at pos t
        for (int i = tid; i < 16 * 256; i += 384) {
            int tok = i >> 8, cc = i & 255;
            int h = cc >> 6, c = cc & 63, j = c & 31;
            int t = t0 + tok;
            float r = rq_s[tok * 4 + h];
            float x1 = o_s[tok*384 + h*64 + j]      * r * gq[h*64 + j];
            float x2 = o_s[tok*384 + h*64 + j + 32] * r * gq[h*64 + j + 32];
            float cs = g_cos[t*32 + j], sn = g_sin[t*32 + j];
            g_Q[((size_t)b*TLEN + t) * 256 + cc] = (c < 32) ? (x1*cs - x2*sn)
                                                            : (x1*sn + x2*cs);
        }
        // sliding K/V at pos TC + t
        for (int i = tid; i < 16 * 64; i += 384) {
            int tok = i >> 6, c = i & 63, j = c & 31;
            int t = t0 + tok, pos = TC + t;
            float r = rkv_s[tok];
            float x1 = o_s[tok*384 + 256 + j]      * r;
            float x2 = o_s[tok*384 + 256 + j + 32] * r;
            float cs = g_cos[pos*32 + j], sn = g_sin[pos*32 + j];
            float k1 = x1*gk[j], k2 = x2*gk[j+32];
            float v1 = x1*gv[j], v2 = x2*gv[j+32];
            size_t o = ((size_t)b*SEQ + pos) * 64 + c;
            g_K[o] = (c < 32) ? (k1*cs - k2*sn) : (k1*sn + k2*cs);
            g_V[o] = (c < 32) ? (v1*cs - v2*sn) : (v1*sn + v2*cs);
        }
        // Q_I = H_dc @ W_IUQ  (H_dc = cols 320..383)
        for (int i = tid; i < 16 * 128; i += 384) {
            int tok = i >> 7, c = i & 127;
            const float* hd = &o_s[tok*384 + 320];
            float a = 0.f;
#pragma unroll 4
            for (int k = 0; k < 64; k++) a += hd[k] * W_IUQ[k*128 + c];
            g_QI[((size_t)b*TLEN + t0 + tok) * 128 + c] = a;
        }
        if (tid < 64) {                        // W_Iw = H_dc @ W_w
            int tok = tid >> 2, c = tid & 3;
            const float* hd = &o_s[tok*384 + 320];
            float a = 0.f;
            for (int k = 0; k < 64; k++) a += hd[k] * W_w[k*4 + c];
            g_WIw[((size_t)b*TLEN + t0 + tok) * 4 + c] = a;
        }
    } else {
        // ======================= compress path =============================
        float* win    = sm;          // 36*256 = 9216
        float* comp_s = sm + 9216;   // 512
        float* red_s  = sm + 9728;   // 4*96*4 = 1536
        float* rms_s  = sm + 11264;  // 8
        const int cb = blockIdx.x - 256;
        const int b  = cb >> 6;
        const int s0 = (cb & 63) << 3;
        const int row0 = s0 << 2;

        for (int i = tid; i < 36 * DIM; i += 384) {
            int r = row0 + (i >> 8);
            win[i] = (r < TLEN) ? H[((size_t)b*TLEN + r) * DIM + (i & 255)] : 0.f;
        }
        __syncthreads();

        const int col = tid % 96;
        const int sub = tid / 96;     // 0..3
        const int grp = sub >> 1;     // windows ds0..ds0+3
        const int kh  = sub & 1;      // k-half
        const int ds0 = grp << 2;
        const float* Wcol; int ldw;
        if (col < 64) { Wcol = Wc_comp + col;       ldw = 64; }
        else          { Wcol = Wc_idx + (col - 64); ldw = 32; }

        float a0 = 0.f, a1 = 0.f, a2 = 0.f, a3 = 0.f;
        const int k4b = kh << 8;
        for (int k4 = k4b; k4 < k4b + 256; k4++) {
            float w0 = Wcol[(size_t)(4*k4+0) * ldw];
            float w1 = Wcol[(size_t)(4*k4+1) * ldw];
            float w2 = Wcol[(size_t)(4*k4+2) * ldw];
            float w3 = Wcol[(size_t)(4*k4+3) * ldw];
            int lrow = k4 >> 6;
            int coff = (k4 & 63) << 2;
#pragma unroll
            for (int d = 0; d < 4; d++) {
                const float4 wv = *(const float4*)&win[(4*(ds0+d) + lrow) * DIM + coff];
                float s = wv.x*w0 + wv.y*w1 + wv.z*w2 + wv.w*w3;
                if (d == 0) a0 += s; else if (d == 1) a1 += s;
                else if (d == 2) a2 += s; else a3 += s;
            }
        }
        {
            float4* rp = (float4*)&red_s[(sub*96 + col) * 4];
            *rp = make_float4(a0, a1, a2, a3);
        }
        __syncthreads();
        if (kh == 0) {
            float4 mine = *(const float4*)&red_s[(sub*96 + col) * 4];
            float4 othr = *(const float4*)&red_s[((sub+1)*96 + col) * 4];
            float av[4] = { mine.x + othr.x, mine.y + othr.y,
                            mine.z + othr.z, mine.w + othr.w };
#pragma unroll
            for (int d = 0; d < 4; d++) {
                int ds = ds0 + d;
                if (col < 64) comp_s[ds*64 + col] = av[d];
                else g_KI[((size_t)b*TC + s0 + ds) * 32 + (col - 64)] = av[d];
            }
        }
        __syncthreads();
        if (tid < 8) {
            float ss = 0.f;
            for (int c = 0; c < 64; c++) { float v = comp_s[tid*64 + c]; ss += v*v; }
            rms_s[tid] = rsqrtf(ss * (1.f/64.f) + 1e-6f);
        }
        __syncthreads();
        for (int i = tid; i < 8 * 64; i += 384) {
            int ds = i >> 6, c = i & 63, j = c & 31;
            int pos = s0 + ds;
            float r = rms_s[ds];
            float x1 = comp_s[ds*64 + j] * r, x2 = comp_s[ds*64 + j + 32] * r;
            float cs = g_cos[pos*32 + j], sn = g_sin[pos*32 + j];
            float k1 = x1*gk[j], k2 = x2*gk[j+32];
            float v1 = x1*gv[j], v2 = x2*gv[j+32];
            size_t o = ((size_t)b*SEQ + pos) * 64 + c;
            g_K[o] = (c < 32) ? (k1*cs - k2*sn) : (k1*sn + k2*cs);
            g_V[o] = (c < 32) ? (v1*cs - v2*sn) : (v1*sn + v2*cs);
        }
    }
}

// ------------------ K2: fused index scores + top-k -------------------------
// 16 tokens/block, 256 threads; score chunks of 128 s kept in smem, causal-
// bounded; then exact jax.lax.top_k per token from smem.
#define ISTRIDE 514
static __device__ __forceinline__ unsigned long long packkey(float v, int s)
{
    unsigned u = __float_as_uint(v);
    u = (u & 0x80000000u) ? ~u : (u | 0x80000000u);
    return ((unsigned long long)u << 32) | (unsigned)(511 - s);
}

__global__ __launch_bounds__(256) void k_scoretopk()
{
    extern __shared__ float dsm[];
    float* qi_s = dsm;                 // 16*132 = 2112
    float* ki_s = dsm + 2112;          // 128*32 = 4096
    float* i_s  = dsm + 6208;          // 16*514 = 8224
    const int tid = threadIdx.x;
    const int b  = blockIdx.x >> 7;
    const int r  = blockIdx.x & 127;
    const int t0 = (127 - r) << 4;     // heavy blocks first
    const int nchunk = (((t0 + 15) >> 2) + 1 + 127) >> 7;

    for (int i = tid; i < 16 * 128; i += 256)
        qi_s[(i >> 7) * 132 + (i & 127)] =
            g_QI[((size_t)b*TLEN + t0 + (i >> 7)) * 128 + (i & 127)];

    const int tok = tid & 15;
    const int sg  = tid >> 4;
    const float4 wIw = *(const float4*)&g_WIw[((size_t)b*TLEN + t0 + tok) * 4];

    for (int c = 0; c < nchunk; c++) {
        const int s0 = c << 7;
        __syncthreads();                       // prior compute done (or qi load)
        for (int i = tid; i < 128 * 32; i += 256)
            ki_s[i] = g_KI[((size_t)b*TC + s0) * 32 + i];
        __syncthreads();

        float acc[4][8];
#pragma unroll
        for (int h = 0; h < 4; h++)
#pragma unroll
            for (int j = 0; j < 8; j++) acc[h][j] = 0.f;
#pragma unroll
        for (int c4 = 0; c4 < 8; c4++) {
            float4 q4[4];
#pragma unroll
            for (int h = 0; h < 4; h++)
                q4[h] = *(const float4*)&qi_s[tok*132 + h*32 + c4*4];
#pragma unroll
            for (int j = 0; j < 8; j++) {
                const float4 kv = *(const float4*)&ki_s[(sg*8 + j)*32 + c4*4];
#pragma unroll
                for (int h = 0; h < 4; h++)
                    acc[h][j] += q4[h].x*kv.x + q4[h].y*kv.y + q4[h].z*kv.z + q4[h].w*kv.w;
            }
        }
#pragma unroll
        for (int j = 0; j < 8; j++) {
            float v = wIw.x*fmaxf(acc[0][j],0.f) + wIw.y*fmaxf(acc[1][j],0.f)
                    + wIw.z*fmaxf(acc[2][j],0.f) + wIw.w*fmaxf(acc[3][j],0.f);
            i_s[tok*ISTRIDE + s0 + sg*8 + j] = v;
        }
    }
    __syncthreads();

    // ---- top-k: 8 warps, each 2 tokens ----
    const int w = tid >> 5, l = tid & 31;
#pragma unroll
    for (int rep = 0; rep < 2; rep++) {
        const int tk = w * 2 + rep;
        const int t  = t0 + tk;
        const float* Irow = &i_s[tk * ISTRIDE];
        unsigned long long keys[16];
#pragma unroll
        for (int k = 0; k < 16; k++) {
            int s = l + 32*k;
            float v = (4*s <= t) ? Irow[s] : fneginf();
            keys[k] = packkey(v, s);
        }
#pragma unroll 1
        for (int i = 0; i < KTOP; i++) {
            unsigned long long best = 0ull;
#pragma unroll
            for (int k = 0; k < 16; k++) best = max(best, keys[k]);
#pragma unroll
            for (int off = 16; off; off >>= 1)
                best = max(best, __shfl_xor_sync(0xffffffffu, best, off));
            int s_win = 511 - (int)(best & 0xffffffffull);
            if (l == 0) g_top[((size_t)b*TLEN + t) * KTOP + i] = s_win;
            if ((s_win & 31) == l) keys[s_win >> 5] = 0ull;
        }
    }
}

// ------------------ K3: sparse attention + inverse rope + projections ------
__global__ __launch_bounds__(512) void k_attn(
    const float* __restrict__ Wg0, const float* __restrict__ bg0,
    const float* __restrict__ Wg1, const float* __restrict__ bg1,
    const float* __restrict__ Wout, const float* __restrict__ bout,
    float* __restrict__ OUT)
{
    __shared__ float qo_s[16 * 256];       // Q tile, then (aliased) rotated O tile
    __shared__ float g_s[16 * 128];
    __shared__ float p_s[16 * 4 * 24];
    __shared__ int   pos_s[16 * 24];
    const int tid = threadIdx.x;
    const int b  = blockIdx.x >> 7;
    const int t0 = (blockIdx.x & 127) << 4;

    for (int i = tid; i < 16 * 256; i += 512)
        qo_s[i] = g_Q[((size_t)b*TLEN + t0) * 256 + i];
    __syncthreads();

    {   // ---- attention: warp w -> token t0+w ----
        const int w = tid >> 5, l = tid & 31;
        const int t = t0 + w;
        const int nsl = (t + 1 < 16) ? (t + 1) : 16;
        const int nkey = 8 + nsl;
        int row = -1;
        if (l < 8)          row = g_top[((size_t)b*TLEN + t) * KTOP + l];
        else if (l < nkey)  row = TC + t - (l - 8);
        if (l < 24) pos_s[w*24 + l] = (row >= 0) ? row : 0;

        float dh[4] = {0.f, 0.f, 0.f, 0.f};
        if (row >= 0) {
            const float4* kp = (const float4*)(g_K + ((size_t)b*SEQ + row) * 64);
#pragma unroll
            for (int c4 = 0; c4 < 16; c4++) {
                float4 kv = kp[c4];
#pragma unroll
                for (int h = 0; h < 4; h++) {
                    float4 q4 = *(const float4*)&qo_s[w*256 + h*64 + c4*4];
                    dh[h] += q4.x*kv.x + q4.y*kv.y + q4.z*kv.z + q4.w*kv.w;
                }
            }
        }
#pragma unroll
        for (int h = 0; h < 4; h++) {
            float s = (row >= 0) ? dh[h] * 0.125f : fneginf();
            float m = s;
#pragma unroll
            for (int off = 16; off; off >>= 1)
                m = fmaxf(m, __shfl_xor_sync(0xffffffffu, m, off));
            float e = expf(s - m);
            float sum = e;
#pragma unroll
            for (int off = 16; off; off >>= 1)
                sum += __shfl_xor_sync(0xffffffffu, sum, off);
            float p = e / sum;                 // p == 0 for invalid lanes
            if (l < 24) p_s[w*96 + h*24 + l] = p;
        }
        __syncwarp();

        // O accumulation: fully-unrolled 24-key loop (padded keys have p=0)
        float o1[4] = {0,0,0,0}, o2[4] = {0,0,0,0};
#pragma unroll
        for (int j = 0; j < 24; j++) {
            int rj = pos_s[w*24 + j];
            const float* vp = g_V + ((size_t)b*SEQ + rj) * 64;
            float v1 = vp[l], v2 = vp[l + 32];
#pragma unroll
            for (int h = 0; h < 4; h++) {
                float p = p_s[w*96 + h*24 + j];
                o1[h] += p * v1;
                o2[h] += p * v2;
            }
        }
        float cs = g_cos[t*32 + l], sn = g_sin[t*32 + l];
        __syncwarp();   // all lanes done reading qo_s[w] before overwrite
#pragma unroll
        for (int h = 0; h < 4; h++) {
            qo_s[w*256 + h*64 + l]      =  o1[h]*cs + o2[h]*sn;
            qo_s[w*256 + h*64 + 32 + l] = -o1[h]*sn + o2[h]*cs;
        }
    }
    __syncthreads();

    // ---- gate projections: g = [O0@Wg0+bg0 ; O1@Wg1+bg1] ----
    {
        const int col = tid & 127;
        const int tq  = tid >> 7;               // 4 tokens each
        const int c   = col & 63;
        const float* Wg = (col < 64) ? Wg0 : Wg1;
        const float  bb = (col < 64) ? bg0[c] : bg1[c];
        const int obase = (col < 64) ? 0 : 128;
        float a[4] = {bb, bb, bb, bb};
#pragma unroll 4
        for (int k = 0; k < 128; k++) {
            float wv = Wg[k*64 + c];
#pragma unroll
            for (int u = 0; u < 4; u++)
                a[u] += qo_s[(tq*4 + u)*256 + obase + k] * wv;
        }
#pragma unroll
        for (int u = 0; u < 4; u++) g_s[(tq*4 + u)*128 + col] = a[u];
    }
    __syncthreads();

    // ---- final: out = p_all @ Wout + bout ----
    {
        const int col = tid & 255;
        const int tq  = tid >> 8;               // 8 tokens each
        float bb = bout[col];
        float a[8] = {bb, bb, bb, bb, bb, bb, bb, bb};
#pragma unroll 4
        for (int k = 0; k < 128; k++) {
            float wv = Wout[k*256 + col];
#pragma unroll
            for (int u = 0; u < 8; u++)
                a[u] += g_s[(tq*8 + u)*128 + k] * wv;
        }
#pragma unroll
        for (int u = 0; u < 8; u++)
            OUT[((size_t)b*TLEN + t0 + tq*8 + u) * DIM + col] = a[u];
    }
}

// ----------------------------- launcher ------------------------------------
extern "C" void kernel_launch(void* const* d_in, const int* in_sizes, int n_in,
                              void* d_out, int out_size)
{
    const float* H       = (const float*)d_in[0];
    const float* Wc_comp = (const float*)d_in[1];
    const float* Wc_idx  = (const float*)d_in[2];
    const float* W_DQ    = (const float*)d_in[3];
    const float* W_IUQ   = (const float*)d_in[4];
    const float* W_w     = (const float*)d_in[5];
    const float* W_Q     = (const float*)d_in[6];
    const float* W_KV    = (const float*)d_in[7];
    const float* gq      = (const float*)d_in[8];
    const float* gk      = (const float*)d_in[9];
    const float* gv      = (const float*)d_in[10];
    const float* Wg0     = (const float*)d_in[11];
    const float* bg0     = (const float*)d_in[12];
    const float* Wg1     = (const float*)d_in[13];
    const float* bg1     = (const float*)d_in[14];
    const float* Wout    = (const float*)d_in[15];
    const float* bout    = (const float*)d_in[16];
    float* OUT = (float*)d_out;

    static int smem_set = 0;
    if (!smem_set) {
        cudaFuncSetAttribute(k_scoretopk,
                             cudaFuncAttributeMaxDynamicSharedMemorySize, 57728);
        smem_set = 1;
    }

    k_tables<<<(SEQ * 32 + 255) / 256, 256>>>();
    k_pre<<<256 + 128, 384>>>(H, Wc_comp, Wc_idx, W_DQ, W_IUQ, W_w, W_Q, W_KV,
                              gq, gk, gv);
    k_scoretopk<<<BATCH * 128, 256, 57728>>>();
    k_attn<<<BATCH * 128, 512>>>(Wg0, bg0, Wg1, bg1, Wout, bout, OUT);
}